// round 11
// baseline (speedup 1.0000x reference)
#include <cuda_runtime.h>
#include <cuda_fp16.h>
#include <math.h>
#include <stdint.h>

// ---------------------------------------------------------------------------
// Self_Attention: N=4096 tokens, D=4096, H=8 heads, DH=512
// Round 11: fp16-accumulator MMA (2x HMMA rate) with per-K16 fp32 promote.
// ---------------------------------------------------------------------------
#define NTOK 4096
#define DMODEL 4096
#define NHEADS 8
#define DHEAD 512
#define QKV_N (3 * DMODEL)
#define ATTN_SCALE 0.04419417382415922f  // 1/sqrt(512)

__device__ __half g_QKV[(size_t)NTOK * QKV_N];      // fp16 [token][Q|K|V]
__device__ float g_bqkv[QKV_N];
__device__ __half g_Xh[(size_t)NTOK * DMODEL];
__device__ __half g_R1h[(size_t)NTOK * DMODEL];
__device__ __half g_W[(size_t)4 * DMODEL * DMODEL]; // [Wq|Wk|Wv|Wfc], each [N,K] fp16
__device__ int g_seg_start[NTOK];
__device__ int g_seg_end[NTOK];

// ---------------------------------------------------------------------------
// PTX helpers
// ---------------------------------------------------------------------------
__device__ __forceinline__ uint32_t smem_u32(const void* p) {
    return (uint32_t)__cvta_generic_to_shared(p);
}
__device__ __forceinline__ uint32_t swz128(uint32_t off) {
    return off ^ ((off >> 3) & 0x70);
}
__device__ __forceinline__ void cp16(uint32_t s, const void* g) {
    asm volatile("cp.async.cg.shared.global [%0], [%1], 16;\n" :: "r"(s), "l"(g));
}
__device__ __forceinline__ void cp_commit() {
    asm volatile("cp.async.commit_group;\n" ::: "memory");
}
__device__ __forceinline__ void cp_wait0() {
    asm volatile("cp.async.wait_group 0;\n" ::: "memory");
}
__device__ __forceinline__ void cp_wait1() {
    asm volatile("cp.async.wait_group 1;\n" ::: "memory");
}
__device__ __forceinline__ void ldsm4(uint32_t* r, uint32_t addr) {
    asm volatile("ldmatrix.sync.aligned.m8n8.x4.shared.b16 {%0,%1,%2,%3}, [%4];"
                 : "=r"(r[0]), "=r"(r[1]), "=r"(r[2]), "=r"(r[3]) : "r"(addr));
}
// fp16-accumulator MMA (2x rate on legacy HMMA path); C = 0
__device__ __forceinline__ void mma_f16acc(uint32_t& d0, uint32_t& d1,
                                           const uint32_t* a, uint32_t b0, uint32_t b1) {
    asm volatile(
        "mma.sync.aligned.m16n8k16.row.col.f16.f16.f16.f16 "
        "{%0,%1}, {%2,%3,%4,%5}, {%6,%7}, {%8,%9};"
        : "=r"(d0), "=r"(d1)
        : "r"(a[0]), "r"(a[1]), "r"(a[2]), "r"(a[3]), "r"(b0), "r"(b1),
          "r"(0u), "r"(0u));
}

// ---------------------------------------------------------------------------
// Segment table builder: binary search per token.
// ---------------------------------------------------------------------------
__global__ void build_seg_kernel(const int* __restrict__ nr, int count) {
    __shared__ int starts[160];
    __shared__ int nseg;
    if (count > 128) count = 128;
    if (threadIdx.x == 0) {
        long long s32 = 0;
        for (int i = 0; i < count; i++) s32 += nr[i];
        int is64 = (s32 != (long long)NTOK) ? 1 : 0;
        int acc = 0;
        for (int i = 0; i < count; i++) {
            starts[i] = acc;
            acc += is64 ? nr[2 * i] : nr[i];
        }
        starts[count] = acc;
        nseg = count;
    }
    __syncthreads();
    const int ns = nseg;
    const int t = blockIdx.x * 256 + threadIdx.x;
    if (t >= NTOK) return;
    int lo = 0, hi = ns;
    while (hi - lo > 1) {
        int mid = (lo + hi) >> 1;
        if (starts[mid] <= t) lo = mid; else hi = mid;
    }
    g_seg_start[t] = starts[lo];
    g_seg_end[t] = starts[lo + 1];
}

// ---------------------------------------------------------------------------
// fp32 -> fp16 convert
// ---------------------------------------------------------------------------
__global__ __launch_bounds__(256)
void convert_h(const float* __restrict__ src, __half* __restrict__ dst, int n4) {
    int i = blockIdx.x * blockDim.x + threadIdx.x;
    if (i >= n4) return;
    float4 v = reinterpret_cast<const float4*>(src)[i];
    __half2 a = __floats2half2_rn(v.x, v.y);
    __half2 b = __floats2half2_rn(v.z, v.w);
    uint2 o;
    o.x = *reinterpret_cast<uint32_t*>(&a);
    o.y = *reinterpret_cast<uint32_t*>(&b);
    reinterpret_cast<uint2*>(dst)[i] = o;
}

// ---------------------------------------------------------------------------
// Weight transpose+convert: grid.z=4 selects Wq/Wk/Wv/Wfc
// ---------------------------------------------------------------------------
__global__ __launch_bounds__(256)
void transpose_conv4(const float* __restrict__ W0, const float* __restrict__ W1,
                     const float* __restrict__ W2, const float* __restrict__ W3,
                     __half* __restrict__ T) {
    const float* W = (blockIdx.z == 0) ? W0 : (blockIdx.z == 1 ? W1
                     : (blockIdx.z == 2 ? W2 : W3));
    __half* dst = T + (size_t)blockIdx.z * DMODEL * DMODEL;
    __shared__ float t[32][33];
    int n0 = blockIdx.x * 32;
    int k0 = blockIdx.y * 32;
    int tx = threadIdx.x & 31;
    int ty = threadIdx.x >> 5;
#pragma unroll
    for (int j = 0; j < 32; j += 8)
        t[ty + j][tx] = W[(size_t)(k0 + ty + j) * DMODEL + n0 + tx];
    __syncthreads();
#pragma unroll
    for (int j = 0; j < 32; j += 8) {
        float v = t[tx][ty + j];
        dst[(size_t)(n0 + ty + j) * DMODEL + k0 + tx] = __float2half_rn(v);
    }
}

__global__ void concat_bias(const float* __restrict__ bq, const float* __restrict__ bk,
                            const float* __restrict__ bv, float* __restrict__ dst) {
    int i = blockIdx.x * 256 + threadIdx.x;
    if (i >= QKV_N) return;
    dst[i] = (i < DMODEL) ? bq[i] : (i < 2 * DMODEL ? bk[i - DMODEL] : bv[i - 2 * DMODEL]);
}

// ---------------------------------------------------------------------------
// Persistent fp16 HMMA GEMM (f16 accumulate + fp32 promote):
// C[M,Ntot] = A @ B^T + bias (+ res fp16)
// CTA 256x128, 8 warps (4x2), warp 64x64, BK=128 (2x64 sub), 2-stage.
// ---------------------------------------------------------------------------
#define GBM 256
#define GBN 128
#define GBK 128
#define GK DMODEL
#define NCHUNK (GK / GBK)          // 32
#define A_SUB 32768
#define B_SUB 16384
#define STAGE_BYTES (2 * A_SUB + 2 * B_SUB)   // 98304
#define GEMM_SMEM (2 * STAGE_BYTES)           // 196608
#define EPI_STRIDE 132
#define NTM (NTOK / GBM)           // 16

template <int HALF_OUT>
__global__ __launch_bounds__(256, 1)
void gemm_f16(const __half* __restrict__ Ah, const __half* __restrict__ Bh,
              const float* __restrict__ bias, const __half* __restrict__ resh,
              void* __restrict__ Cv, int Ntot, int ntiles) {
    extern __shared__ char smem[];
    const uint32_t sb = smem_u32(smem);
    const int tid = threadIdx.x;
    const int wid = tid >> 5;
    const int lane = tid & 31;
    const int warpM = wid >> 1;
    const int warpN = wid & 1;
    const int lrow = lane & 15;
    const int lcol = (lane >> 4) * 16;
    const size_t rowstride = (size_t)GK * 2;

    for (int tile = blockIdx.x; tile < ntiles; tile += gridDim.x) {
        const int tm = tile % NTM;
        const int tn = tile / NTM;
        const char* pAh = (const char*)(Ah + (size_t)tm * GBM * GK);
        const char* pBh = (const char*)(Bh + (size_t)tn * GBN * GK);

        auto issue_loads = [&](int chunk, int s) {
            const uint32_t base = sb + s * STAGE_BYTES;
            const size_t koff = (size_t)chunk * GBK * 2;
#pragma unroll
            for (int sub = 0; sub < 2; sub++) {
                const uint32_t ab = base + sub * A_SUB;
                const uint32_t bb = base + 2 * A_SUB + sub * B_SUB;
                const size_t ko = koff + sub * 128;
#pragma unroll
                for (int j = 0; j < 8; j++) {
                    int u = tid + 256 * j;
                    int row = u >> 3;
                    int c = (u & 7) * 16;
                    uint32_t so = swz128((uint32_t)(row * 128 + c));
                    cp16(ab + so, pAh + (size_t)row * rowstride + ko + c);
                }
#pragma unroll
                for (int j = 0; j < 4; j++) {
                    int u = tid + 256 * j;
                    int row = u >> 3;
                    int c = (u & 7) * 16;
                    uint32_t so = swz128((uint32_t)(row * 128 + c));
                    cp16(bb + so, pBh + (size_t)row * rowstride + ko + c);
                }
            }
            cp_commit();
        };

        float acc[4][8][4];
#pragma unroll
        for (int mt = 0; mt < 4; mt++)
#pragma unroll
            for (int nt = 0; nt < 8; nt++)
#pragma unroll
                for (int e = 0; e < 4; e++) acc[mt][nt][e] = 0.0f;

        issue_loads(0, 0);
        issue_loads(1, 1);

        for (int i = 0; i < NCHUNK; i++) {
            if (i + 1 < NCHUNK) cp_wait1(); else cp_wait0();
            __syncthreads();
            const int s = i & 1;
            const uint32_t base = sb + s * STAGE_BYTES;

#pragma unroll
            for (int ks = 0; ks < 8; ks++) {
                const int sub = ks >> 2;
                const int kb = (ks & 3) * 32 + lcol;
                const uint32_t bA = base + sub * A_SUB;
                const uint32_t bB = base + 2 * A_SUB + sub * B_SUB;
                uint32_t aH[4][4], bH[4][4];
#pragma unroll
                for (int mt = 0; mt < 4; mt++) {
                    int row = warpM * 64 + mt * 16 + lrow;
                    ldsm4(aH[mt], bA + swz128((uint32_t)(row * 128 + kb)));
                }
#pragma unroll
                for (int p = 0; p < 4; p++) {
                    int row = warpN * 64 + p * 16 + lrow;
                    ldsm4(bH[p], bB + swz128((uint32_t)(row * 128 + kb)));
                }
#pragma unroll
                for (int mt = 0; mt < 4; mt++) {
#pragma unroll
                    for (int nt = 0; nt < 8; nt++) {
                        const int p = nt >> 1;
                        const int o = nt & 1;
                        uint32_t d0, d1;
                        mma_f16acc(d0, d1, aH[mt], bH[p][o], bH[p][o + 2]);
                        const float2 lo2 = __half22float2(*reinterpret_cast<__half2*>(&d0));
                        const float2 hi2 = __half22float2(*reinterpret_cast<__half2*>(&d1));
                        acc[mt][nt][0] += lo2.x;
                        acc[mt][nt][1] += lo2.y;
                        acc[mt][nt][2] += hi2.x;
                        acc[mt][nt][3] += hi2.y;
                    }
                }
            }
            __syncthreads();
            if (i + 2 < NCHUNK) issue_loads(i + 2, s);
        }
        __syncthreads();

        // ---- epilogue ----
        float* sf = reinterpret_cast<float*>(smem);
        const int g = lane >> 2;
        const int t2 = (lane & 3) * 2;
#pragma unroll
        for (int mt = 0; mt < 4; mt++) {
#pragma unroll
            for (int nt = 0; nt < 8; nt++) {
                int row = warpM * 64 + mt * 16 + g;
                int col = warpN * 64 + nt * 8 + t2;
                sf[row * EPI_STRIDE + col] = acc[mt][nt][0];
                sf[row * EPI_STRIDE + col + 1] = acc[mt][nt][1];
                sf[(row + 8) * EPI_STRIDE + col] = acc[mt][nt][2];
                sf[(row + 8) * EPI_STRIDE + col + 1] = acc[mt][nt][3];
            }
        }
        __syncthreads();

        const int orow = tid;
        const size_t gbase = (size_t)(tm * GBM + orow) * Ntot + (size_t)tn * GBN;
        const size_t rbase = (size_t)(tm * GBM + orow) * DMODEL + (size_t)tn * GBN;
#pragma unroll
        for (int j = 0; j < 32; j++) {
            int col = j * 4;
            float4 v;
            v.x = sf[orow * EPI_STRIDE + col + 0] + bias[tn * GBN + col + 0];
            v.y = sf[orow * EPI_STRIDE + col + 1] + bias[tn * GBN + col + 1];
            v.z = sf[orow * EPI_STRIDE + col + 2] + bias[tn * GBN + col + 2];
            v.w = sf[orow * EPI_STRIDE + col + 3] + bias[tn * GBN + col + 3];
            if (HALF_OUT) {
                __half2 h0 = __floats2half2_rn(v.x, v.y);
                __half2 h1 = __floats2half2_rn(v.z, v.w);
                uint2 o;
                o.x = *reinterpret_cast<uint32_t*>(&h0);
                o.y = *reinterpret_cast<uint32_t*>(&h1);
                *reinterpret_cast<uint2*>((__half*)Cv + gbase + col) = o;
            } else {
                if (resh != nullptr) {
                    uint2 r2 = *reinterpret_cast<const uint2*>(resh + rbase + col);
                    float2 ra = __half22float2(*reinterpret_cast<__half2*>(&r2.x));
                    float2 rb = __half22float2(*reinterpret_cast<__half2*>(&r2.y));
                    v.x += ra.x; v.y += ra.y; v.z += rb.x; v.w += rb.y;
                }
                *reinterpret_cast<float4*>((float*)Cv + gbase + col) = v;
            }
        }
        __syncthreads();
    }
}

// ---------------------------------------------------------------------------
// Block-diagonal attention, cp.async double-buffered smem K/V.
// Block = 32 queries x 1 head. Writes only fp16 R1h (context + X residual).
// ---------------------------------------------------------------------------
#define ACH 32
#define KV_BYTES (ACH * DHEAD * 2)
#define ABUF_BYTES (2 * KV_BYTES)
#define ATTN_SMEM (2 * ABUF_BYTES)            // 128 KB

__global__ __launch_bounds__(256)
void attn_kernel(const __half* __restrict__ QKV, const float* __restrict__ X,
                 __half* __restrict__ R1h) {
    extern __shared__ char smem[];
    const uint32_t sb = smem_u32(smem);

    const int tid = threadIdx.x;
    const int lane = tid & 31;
    const int warp = tid >> 5;
    const int q0b = blockIdx.x * 32;
    const int q0 = q0b + warp * 4;
    const int h = blockIdx.y;
    const int hoff = h * DHEAD;

    const int bjmin = g_seg_start[q0b];
    const int bjmax = g_seg_end[q0b + 31];
    const int nch = (bjmax - bjmin + ACH - 1) / ACH;

    int s0[4], s1[4];
    __half2 q2[4][8];
#pragma unroll
    for (int i = 0; i < 4; i++) {
        const int q = q0 + i;
        s0[i] = g_seg_start[q];
        s1[i] = g_seg_end[q];
        const __half2* qrow = (const __half2*)(QKV + (size_t)q * QKV_N + hoff);
#pragma unroll
        for (int d = 0; d < 8; d++) q2[i][d] = qrow[lane + 32 * d];
    }
    const int wjmin = min(min(s0[0], s0[1]), min(s0[2], s0[3]));
    const int wjmax = max(max(s1[0], s1[1]), max(s1[2], s1[3]));

    float m[4] = {-1e30f, -1e30f, -1e30f, -1e30f};
    float l[4] = {0.f, 0.f, 0.f, 0.f};
    float accv[4][16];
#pragma unroll
    for (int i = 0; i < 4; i++)
#pragma unroll
        for (int d = 0; d < 16; d++) accv[i][d] = 0.0f;

    auto load_chunk = [&](int c, int buf) {
        const uint32_t kb = sb + buf * ABUF_BYTES;
        const uint32_t vb = kb + KV_BYTES;
#pragma unroll
        for (int j = 0; j < 8; j++) {
            int e = tid + 256 * j;
            int r = e >> 6;
            int u = (e & 63) * 16;
            int rc = min(c + r, bjmax - 1);
            const char* kg = (const char*)(QKV + (size_t)rc * QKV_N + DMODEL + hoff) + u;
            const char* vg = (const char*)(QKV + (size_t)rc * QKV_N + 2 * DMODEL + hoff) + u;
            cp16(kb + r * 1024 + u, kg);
            cp16(vb + r * 1024 + u, vg);
        }
        cp_commit();
    };

    load_chunk(bjmin, 0);
    if (nch > 1) load_chunk(bjmin + ACH, 1);

    for (int ci = 0; ci < nch; ci++) {
        const int c = bjmin + ci * ACH;
        const int nrows = min(ACH, bjmax - c);
        if (ci + 1 < nch) cp_wait1(); else cp_wait0();
        __syncthreads();

        const int buf = ci & 1;
        const __half* Ks = (const __half*)(smem + buf * ABUF_BYTES);
        const __half* Vs = (const __half*)(smem + buf * ABUF_BYTES + KV_BYTES);

        const int j0 = max(c, wjmin);
        const int j1 = min(c + nrows, wjmax);
        for (int j = j0; j < j1; j++) {
            const __half2* kr = (const __half2*)(Ks + (j - c) * DHEAD);
            float s[4] = {0.f, 0.f, 0.f, 0.f};
#pragma unroll
            for (int d = 0; d < 8; d++) {
                const float2 kf = __half22float2(kr[lane + 32 * d]);
#pragma unroll
                for (int i = 0; i < 4; i++) {
                    const float2 qf = __half22float2(q2[i][d]);
                    s[i] = fmaf(qf.x, kf.x, s[i]);
                    s[i] = fmaf(qf.y, kf.y, s[i]);
                }
            }
#pragma unroll
            for (int off = 16; off > 0; off >>= 1) {
#pragma unroll
                for (int i = 0; i < 4; i++)
                    s[i] += __shfl_xor_sync(0xFFFFFFFFu, s[i], off);
            }

            const __half2* vr = (const __half2*)(Vs + (j - c) * DHEAD);
            float2 vf[8];
#pragma unroll
            for (int d = 0; d < 8; d++) vf[d] = __half22float2(vr[lane + 32 * d]);

#pragma unroll
            for (int i = 0; i < 4; i++) {
                if (j >= s0[i] && j < s1[i]) {
                    const float sc = s[i] * ATTN_SCALE;
                    const float mn = fmaxf(m[i], sc);
                    const float ce = __expf(m[i] - mn);
                    const float p = __expf(sc - mn);
                    l[i] = l[i] * ce + p;
#pragma unroll
                    for (int d = 0; d < 8; d++) {
                        accv[i][2 * d] = fmaf(accv[i][2 * d], ce, p * vf[d].x);
                        accv[i][2 * d + 1] = fmaf(accv[i][2 * d + 1], ce, p * vf[d].y);
                    }
                    m[i] = mn;
                }
            }
        }
        __syncthreads();
        if (ci + 2 < nch) load_chunk(bjmin + (ci + 2) * ACH, buf);
    }

#pragma unroll
    for (int i = 0; i < 4; i++) {
        const int q = q0 + i;
        const float inv = 1.0f / l[i];
        const float2* xr = (const float2*)(X + (size_t)q * DMODEL + hoff);
        __half2* hrow = (__half2*)(R1h + (size_t)q * DMODEL + hoff);
#pragma unroll
        for (int d = 0; d < 8; d++) {
            const float2 x2 = xr[lane + 32 * d];
            hrow[lane + 32 * d] = __floats2half2_rn(
                accv[i][2 * d] * inv + x2.x, accv[i][2 * d + 1] * inv + x2.y);
        }
    }
}

// ---------------------------------------------------------------------------
// kernel_launch
// ---------------------------------------------------------------------------
extern "C" void kernel_launch(void* const* d_in, const int* in_sizes, int n_in,
                              void* d_out, int out_size) {
    const float* X   = (const float*)d_in[0];
    const int*   nr  = (const int*)d_in[1];
    const float* Wq  = (const float*)d_in[2];
    const float* bq  = (const float*)d_in[3];
    const float* Wk  = (const float*)d_in[4];
    const float* bk  = (const float*)d_in[5];
    const float* Wv  = (const float*)d_in[6];
    const float* bv  = (const float*)d_in[7];
    const float* Wfc = (const float*)d_in[8];
    const float* bfc = (const float*)d_in[9];
    float* out = (float*)d_out;

    float *bqkv;
    __half *QKV, *Xh, *R1h, *W;
    cudaGetSymbolAddress((void**)&QKV, g_QKV);
    cudaGetSymbolAddress((void**)&bqkv, g_bqkv);
    cudaGetSymbolAddress((void**)&Xh, g_Xh);
    cudaGetSymbolAddress((void**)&R1h, g_R1h);
    cudaGetSymbolAddress((void**)&W, g_W);

    cudaFuncSetAttribute(gemm_f16<0>, cudaFuncAttributeMaxDynamicSharedMemorySize, GEMM_SMEM);
    cudaFuncSetAttribute(gemm_f16<1>, cudaFuncAttributeMaxDynamicSharedMemorySize, GEMM_SMEM);
    cudaFuncSetAttribute(attn_kernel, cudaFuncAttributeMaxDynamicSharedMemorySize, ATTN_SMEM);

    int nsm = 148;
    cudaDeviceGetAttribute(&nsm, cudaDevAttrMultiProcessorCount, 0);

    const int n4 = (NTOK * DMODEL) / 4;

    // prep
    concat_bias<<<(QKV_N + 255) / 256, 256>>>(bq, bk, bv, bqkv);
    convert_h<<<n4 / 256, 256>>>(X, Xh, n4);
    dim3 tgrid4(DMODEL / 32, DMODEL / 32, 4);
    transpose_conv4<<<tgrid4, 256>>>(Wq, Wk, Wv, Wfc, W);
    build_seg_kernel<<<NTOK / 256, 256>>>(nr, in_sizes[1]);

    // fused QKV projection -> fp16 (persistent)
    const int qkv_tiles = NTM * (QKV_N / GBN);
    gemm_f16<1><<<(qkv_tiles < nsm ? qkv_tiles : nsm), 256, GEMM_SMEM>>>(
        Xh, W, bqkv, nullptr, QKV, QKV_N, qkv_tiles);

    // attention -> R1h (fp16 context + X residual)
    dim3 agrid(NTOK / 32, NHEADS);
    attn_kernel<<<agrid, 256, ATTN_SMEM>>>(QKV, X, R1h);

    // FC: out = R1h + R1h @ Wfc + bfc (persistent)
    const int fc_tiles = NTM * (DMODEL / GBN);
    gemm_f16<0><<<(fc_tiles < nsm ? fc_tiles : nsm), 256, GEMM_SMEM>>>(
        R1h, W + (size_t)3 * DMODEL * DMODEL, bfc, R1h, out, DMODEL, fc_tiles);
}

// round 12
// speedup vs baseline: 1.3376x; 1.3376x over previous
#include <cuda_runtime.h>
#include <cuda_fp16.h>
#include <math.h>
#include <stdint.h>

// ---------------------------------------------------------------------------
// Self_Attention: N=4096 tokens, D=4096, H=8 heads, DH=512
// Round 12: revert GEMM to fp32-acc (R10); attention 64KB smem (2-3 CTA/SM);
//           vectorized weight transpose; merged seg+bias prep.
// ---------------------------------------------------------------------------
#define NTOK 4096
#define DMODEL 4096
#define NHEADS 8
#define DHEAD 512
#define QKV_N (3 * DMODEL)
#define ATTN_SCALE 0.04419417382415922f  // 1/sqrt(512)

__device__ __half g_QKV[(size_t)NTOK * QKV_N];      // fp16 [token][Q|K|V]
__device__ float g_bqkv[QKV_N];
__device__ __half g_Xh[(size_t)NTOK * DMODEL];
__device__ __half g_R1h[(size_t)NTOK * DMODEL];
__device__ __half g_W[(size_t)4 * DMODEL * DMODEL]; // [Wq|Wk|Wv|Wfc], each [N,K] fp16
__device__ int g_seg_start[NTOK];
__device__ int g_seg_end[NTOK];

// ---------------------------------------------------------------------------
// PTX helpers
// ---------------------------------------------------------------------------
__device__ __forceinline__ uint32_t smem_u32(const void* p) {
    return (uint32_t)__cvta_generic_to_shared(p);
}
__device__ __forceinline__ uint32_t swz128(uint32_t off) {
    return off ^ ((off >> 3) & 0x70);
}
__device__ __forceinline__ void cp16(uint32_t s, const void* g) {
    asm volatile("cp.async.cg.shared.global [%0], [%1], 16;\n" :: "r"(s), "l"(g));
}
__device__ __forceinline__ void cp_commit() {
    asm volatile("cp.async.commit_group;\n" ::: "memory");
}
__device__ __forceinline__ void cp_wait0() {
    asm volatile("cp.async.wait_group 0;\n" ::: "memory");
}
__device__ __forceinline__ void cp_wait1() {
    asm volatile("cp.async.wait_group 1;\n" ::: "memory");
}
__device__ __forceinline__ void ldsm4(uint32_t* r, uint32_t addr) {
    asm volatile("ldmatrix.sync.aligned.m8n8.x4.shared.b16 {%0,%1,%2,%3}, [%4];"
                 : "=r"(r[0]), "=r"(r[1]), "=r"(r[2]), "=r"(r[3]) : "r"(addr));
}
// fp32-accumulate MMA (the proven ~290 TF/s path)
__device__ __forceinline__ void mma_f16(float* d, const uint32_t* a,
                                        uint32_t b0, uint32_t b1) {
    asm volatile(
        "mma.sync.aligned.m16n8k16.row.col.f32.f16.f16.f32 "
        "{%0,%1,%2,%3}, {%4,%5,%6,%7}, {%8,%9}, {%0,%1,%2,%3};"
        : "+f"(d[0]), "+f"(d[1]), "+f"(d[2]), "+f"(d[3])
        : "r"(a[0]), "r"(a[1]), "r"(a[2]), "r"(a[3]), "r"(b0), "r"(b1));
}

// ---------------------------------------------------------------------------
// Merged prep: blocks 0..15 build segment table (binary search per token);
// blocks 16..63 concat the QKV bias.
// ---------------------------------------------------------------------------
__global__ void seg_and_bias_kernel(const int* __restrict__ nr, int count,
                                    const float* __restrict__ bq,
                                    const float* __restrict__ bk,
                                    const float* __restrict__ bv,
                                    float* __restrict__ bqkv) {
    const int b = blockIdx.x;
    if (b >= 16) {
        int i = (b - 16) * 256 + threadIdx.x;
        if (i < QKV_N)
            bqkv[i] = (i < DMODEL) ? bq[i]
                      : (i < 2 * DMODEL ? bk[i - DMODEL] : bv[i - 2 * DMODEL]);
        return;
    }
    __shared__ int starts[160];
    __shared__ int nseg;
    if (count > 128) count = 128;
    if (threadIdx.x == 0) {
        long long s32 = 0;
        for (int i = 0; i < count; i++) s32 += nr[i];
        int is64 = (s32 != (long long)NTOK) ? 1 : 0;
        int acc = 0;
        for (int i = 0; i < count; i++) {
            starts[i] = acc;
            acc += is64 ? nr[2 * i] : nr[i];
        }
        starts[count] = acc;
        nseg = count;
    }
    __syncthreads();
    const int ns = nseg;
    const int t = b * 256 + threadIdx.x;
    int lo = 0, hi = ns;
    while (hi - lo > 1) {
        int mid = (lo + hi) >> 1;
        if (starts[mid] <= t) lo = mid; else hi = mid;
    }
    g_seg_start[t] = starts[lo];
    g_seg_end[t] = starts[lo + 1];
}

// ---------------------------------------------------------------------------
// fp32 -> fp16 convert
// ---------------------------------------------------------------------------
__global__ __launch_bounds__(256)
void convert_h(const float* __restrict__ src, __half* __restrict__ dst, int n4) {
    int i = blockIdx.x * blockDim.x + threadIdx.x;
    if (i >= n4) return;
    float4 v = reinterpret_cast<const float4*>(src)[i];
    __half2 a = __floats2half2_rn(v.x, v.y);
    __half2 b = __floats2half2_rn(v.z, v.w);
    uint2 o;
    o.x = *reinterpret_cast<uint32_t*>(&a);
    o.y = *reinterpret_cast<uint32_t*>(&b);
    reinterpret_cast<uint2*>(dst)[i] = o;
}

// ---------------------------------------------------------------------------
// Vectorized weight transpose+convert: 64x64 tiles, grid.z=4 selects matrix.
// W [K,N] fp32 -> [N,K] fp16.
// ---------------------------------------------------------------------------
__global__ __launch_bounds__(256)
void transpose_conv4(const float* __restrict__ W0, const float* __restrict__ W1,
                     const float* __restrict__ W2, const float* __restrict__ W3,
                     __half* __restrict__ T) {
    const float* W = (blockIdx.z == 0) ? W0 : (blockIdx.z == 1 ? W1
                     : (blockIdx.z == 2 ? W2 : W3));
    __half* dst = T + (size_t)blockIdx.z * DMODEL * DMODEL;
    __shared__ float sm[64][65];
    const int n0 = blockIdx.x * 64;
    const int k0 = blockIdx.y * 64;
    const int tid = threadIdx.x;
    // load 64 k-rows x 64 n-floats (float4 coalesced)
#pragma unroll
    for (int j = 0; j < 4; j++) {
        int u = tid + 256 * j;
        int kr = u >> 4;
        int c4 = (u & 15) * 4;
        float4 v = *reinterpret_cast<const float4*>(
            W + (size_t)(k0 + kr) * DMODEL + n0 + c4);
        sm[kr][c4 + 0] = v.x;
        sm[kr][c4 + 1] = v.y;
        sm[kr][c4 + 2] = v.z;
        sm[kr][c4 + 3] = v.w;
    }
    __syncthreads();
    // store 64 n-rows x 64 k-halves (uint2 = 4 halves, coalesced)
#pragma unroll
    for (int j = 0; j < 4; j++) {
        int u = tid + 256 * j;
        int nr = u >> 4;
        int kg = (u & 15) * 4;
        __half2 h0 = __floats2half2_rn(sm[kg + 0][nr], sm[kg + 1][nr]);
        __half2 h1 = __floats2half2_rn(sm[kg + 2][nr], sm[kg + 3][nr]);
        uint2 o;
        o.x = *reinterpret_cast<uint32_t*>(&h0);
        o.y = *reinterpret_cast<uint32_t*>(&h1);
        *reinterpret_cast<uint2*>(dst + (size_t)(n0 + nr) * DMODEL + k0 + kg) = o;
    }
}

// ---------------------------------------------------------------------------
// Persistent fp16 HMMA GEMM (fp32 accumulate) — reverted to R10:
// C[M,Ntot] = A @ B^T + bias (+ res fp16)
// CTA 256x128, 8 warps (4x2), warp 64x64, BK=128 (2x64 sub), 2-stage.
// ---------------------------------------------------------------------------
#define GBM 256
#define GBN 128
#define GBK 128
#define GK DMODEL
#define NCHUNK (GK / GBK)          // 32
#define A_SUB 32768
#define B_SUB 16384
#define STAGE_BYTES (2 * A_SUB + 2 * B_SUB)   // 98304
#define GEMM_SMEM (2 * STAGE_BYTES)           // 196608
#define EPI_STRIDE 132
#define NTM (NTOK / GBM)           // 16

template <int HALF_OUT>
__global__ __launch_bounds__(256, 1)
void gemm_f16(const __half* __restrict__ Ah, const __half* __restrict__ Bh,
              const float* __restrict__ bias, const __half* __restrict__ resh,
              void* __restrict__ Cv, int Ntot, int ntiles) {
    extern __shared__ char smem[];
    const uint32_t sb = smem_u32(smem);
    const int tid = threadIdx.x;
    const int wid = tid >> 5;
    const int lane = tid & 31;
    const int warpM = wid >> 1;
    const int warpN = wid & 1;
    const int lrow = lane & 15;
    const int lcol = (lane >> 4) * 16;
    const size_t rowstride = (size_t)GK * 2;

    for (int tile = blockIdx.x; tile < ntiles; tile += gridDim.x) {
        const int tm = tile % NTM;
        const int tn = tile / NTM;
        const char* pAh = (const char*)(Ah + (size_t)tm * GBM * GK);
        const char* pBh = (const char*)(Bh + (size_t)tn * GBN * GK);

        auto issue_loads = [&](int chunk, int s) {
            const uint32_t base = sb + s * STAGE_BYTES;
            const size_t koff = (size_t)chunk * GBK * 2;
#pragma unroll
            for (int sub = 0; sub < 2; sub++) {
                const uint32_t ab = base + sub * A_SUB;
                const uint32_t bb = base + 2 * A_SUB + sub * B_SUB;
                const size_t ko = koff + sub * 128;
#pragma unroll
                for (int j = 0; j < 8; j++) {
                    int u = tid + 256 * j;
                    int row = u >> 3;
                    int c = (u & 7) * 16;
                    uint32_t so = swz128((uint32_t)(row * 128 + c));
                    cp16(ab + so, pAh + (size_t)row * rowstride + ko + c);
                }
#pragma unroll
                for (int j = 0; j < 4; j++) {
                    int u = tid + 256 * j;
                    int row = u >> 3;
                    int c = (u & 7) * 16;
                    uint32_t so = swz128((uint32_t)(row * 128 + c));
                    cp16(bb + so, pBh + (size_t)row * rowstride + ko + c);
                }
            }
            cp_commit();
        };

        float acc[4][8][4];
#pragma unroll
        for (int mt = 0; mt < 4; mt++)
#pragma unroll
            for (int nt = 0; nt < 8; nt++)
#pragma unroll
                for (int e = 0; e < 4; e++) acc[mt][nt][e] = 0.0f;

        issue_loads(0, 0);
        issue_loads(1, 1);

        for (int i = 0; i < NCHUNK; i++) {
            if (i + 1 < NCHUNK) cp_wait1(); else cp_wait0();
            __syncthreads();
            const int s = i & 1;
            const uint32_t base = sb + s * STAGE_BYTES;

#pragma unroll
            for (int ks = 0; ks < 8; ks++) {
                const int sub = ks >> 2;
                const int kb = (ks & 3) * 32 + lcol;
                const uint32_t bA = base + sub * A_SUB;
                const uint32_t bB = base + 2 * A_SUB + sub * B_SUB;
                uint32_t aH[4][4], bH[4][4];
#pragma unroll
                for (int mt = 0; mt < 4; mt++) {
                    int row = warpM * 64 + mt * 16 + lrow;
                    ldsm4(aH[mt], bA + swz128((uint32_t)(row * 128 + kb)));
                }
#pragma unroll
                for (int p = 0; p < 4; p++) {
                    int row = warpN * 64 + p * 16 + lrow;
                    ldsm4(bH[p], bB + swz128((uint32_t)(row * 128 + kb)));
                }
#pragma unroll
                for (int mt = 0; mt < 4; mt++) {
#pragma unroll
                    for (int nt = 0; nt < 8; nt++) {
                        const int p = nt >> 1;
                        const int o = nt & 1;
                        mma_f16(acc[mt][nt], aH[mt], bH[p][o], bH[p][o + 2]);
                    }
                }
            }
            __syncthreads();
            if (i + 2 < NCHUNK) issue_loads(i + 2, s);
        }
        __syncthreads();

        // ---- epilogue ----
        float* sf = reinterpret_cast<float*>(smem);
        const int g = lane >> 2;
        const int t2 = (lane & 3) * 2;
#pragma unroll
        for (int mt = 0; mt < 4; mt++) {
#pragma unroll
            for (int nt = 0; nt < 8; nt++) {
                int row = warpM * 64 + mt * 16 + g;
                int col = warpN * 64 + nt * 8 + t2;
                sf[row * EPI_STRIDE + col] = acc[mt][nt][0];
                sf[row * EPI_STRIDE + col + 1] = acc[mt][nt][1];
                sf[(row + 8) * EPI_STRIDE + col] = acc[mt][nt][2];
                sf[(row + 8) * EPI_STRIDE + col + 1] = acc[mt][nt][3];
            }
        }
        __syncthreads();

        const int orow = tid;
        const size_t gbase = (size_t)(tm * GBM + orow) * Ntot + (size_t)tn * GBN;
        const size_t rbase = (size_t)(tm * GBM + orow) * DMODEL + (size_t)tn * GBN;
#pragma unroll
        for (int j = 0; j < 32; j++) {
            int col = j * 4;
            float4 v;
            v.x = sf[orow * EPI_STRIDE + col + 0] + bias[tn * GBN + col + 0];
            v.y = sf[orow * EPI_STRIDE + col + 1] + bias[tn * GBN + col + 1];
            v.z = sf[orow * EPI_STRIDE + col + 2] + bias[tn * GBN + col + 2];
            v.w = sf[orow * EPI_STRIDE + col + 3] + bias[tn * GBN + col + 3];
            if (HALF_OUT) {
                __half2 h0 = __floats2half2_rn(v.x, v.y);
                __half2 h1 = __floats2half2_rn(v.z, v.w);
                uint2 o;
                o.x = *reinterpret_cast<uint32_t*>(&h0);
                o.y = *reinterpret_cast<uint32_t*>(&h1);
                *reinterpret_cast<uint2*>((__half*)Cv + gbase + col) = o;
            } else {
                if (resh != nullptr) {
                    uint2 r2 = *reinterpret_cast<const uint2*>(resh + rbase + col);
                    float2 ra = __half22float2(*reinterpret_cast<__half2*>(&r2.x));
                    float2 rb = __half22float2(*reinterpret_cast<__half2*>(&r2.y));
                    v.x += ra.x; v.y += ra.y; v.z += rb.x; v.w += rb.y;
                }
                *reinterpret_cast<float4*>((float*)Cv + gbase + col) = v;
            }
        }
        __syncthreads();
    }
}

// ---------------------------------------------------------------------------
// Block-diagonal attention, cp.async double-buffered smem K/V.
// Block = 32 queries x 1 head. ACH=16 -> 64KB smem -> 2-3 CTAs/SM.
// ---------------------------------------------------------------------------
#define ACH 16
#define KV_BYTES (ACH * DHEAD * 2)            // 16 KB
#define ABUF_BYTES (2 * KV_BYTES)             // 32 KB
#define ATTN_SMEM (2 * ABUF_BYTES)            // 64 KB

__global__ __launch_bounds__(256, 2)
void attn_kernel(const __half* __restrict__ QKV, const float* __restrict__ X,
                 __half* __restrict__ R1h) {
    extern __shared__ char smem[];
    const uint32_t sb = smem_u32(smem);

    const int tid = threadIdx.x;
    const int lane = tid & 31;
    const int warp = tid >> 5;
    const int q0b = blockIdx.x * 32;
    const int q0 = q0b + warp * 4;
    const int h = blockIdx.y;
    const int hoff = h * DHEAD;

    const int bjmin = g_seg_start[q0b];
    const int bjmax = g_seg_end[q0b + 31];
    const int nch = (bjmax - bjmin + ACH - 1) / ACH;

    int s0[4], s1[4];
    __half2 q2[4][8];
#pragma unroll
    for (int i = 0; i < 4; i++) {
        const int q = q0 + i;
        s0[i] = g_seg_start[q];
        s1[i] = g_seg_end[q];
        const __half2* qrow = (const __half2*)(QKV + (size_t)q * QKV_N + hoff);
#pragma unroll
        for (int d = 0; d < 8; d++) q2[i][d] = qrow[lane + 32 * d];
    }
    const int wjmin = min(min(s0[0], s0[1]), min(s0[2], s0[3]));
    const int wjmax = max(max(s1[0], s1[1]), max(s1[2], s1[3]));

    float m[4] = {-1e30f, -1e30f, -1e30f, -1e30f};
    float l[4] = {0.f, 0.f, 0.f, 0.f};
    float accv[4][16];
#pragma unroll
    for (int i = 0; i < 4; i++)
#pragma unroll
        for (int d = 0; d < 16; d++) accv[i][d] = 0.0f;

    // chunk loader: ACH rows x 64 units for K and V -> 4 cp16/thread/matrix
    auto load_chunk = [&](int c, int buf) {
        const uint32_t kb = sb + buf * ABUF_BYTES;
        const uint32_t vb = kb + KV_BYTES;
#pragma unroll
        for (int j = 0; j < 4; j++) {
            int e = tid + 256 * j;
            int r = e >> 6;
            int u = (e & 63) * 16;
            int rc = min(c + r, bjmax - 1);
            const char* kg = (const char*)(QKV + (size_t)rc * QKV_N + DMODEL + hoff) + u;
            const char* vg = (const char*)(QKV + (size_t)rc * QKV_N + 2 * DMODEL + hoff) + u;
            cp16(kb + r * 1024 + u, kg);
            cp16(vb + r * 1024 + u, vg);
        }
        cp_commit();
    };

    load_chunk(bjmin, 0);
    if (nch > 1) load_chunk(bjmin + ACH, 1);

    for (int ci = 0; ci < nch; ci++) {
        const int c = bjmin + ci * ACH;
        const int nrows = min(ACH, bjmax - c);
        if (ci + 1 < nch) cp_wait1(); else cp_wait0();
        __syncthreads();

        const int buf = ci & 1;
        const __half* Ks = (const __half*)(smem + buf * ABUF_BYTES);
        const __half* Vs = (const __half*)(smem + buf * ABUF_BYTES + KV_BYTES);

        const int j0 = max(c, wjmin);
        const int j1 = min(c + nrows, wjmax);
        for (int j = j0; j < j1; j++) {
            const __half2* kr = (const __half2*)(Ks + (j - c) * DHEAD);
            float s[4] = {0.f, 0.f, 0.f, 0.f};
#pragma unroll
            for (int d = 0; d < 8; d++) {
                const float2 kf = __half22float2(kr[lane + 32 * d]);
#pragma unroll
                for (int i = 0; i < 4; i++) {
                    const float2 qf = __half22float2(q2[i][d]);
                    s[i] = fmaf(qf.x, kf.x, s[i]);
                    s[i] = fmaf(qf.y, kf.y, s[i]);
                }
            }
#pragma unroll
            for (int off = 16; off > 0; off >>= 1) {
#pragma unroll
                for (int i = 0; i < 4; i++)
                    s[i] += __shfl_xor_sync(0xFFFFFFFFu, s[i], off);
            }

            const __half2* vr = (const __half2*)(Vs + (j - c) * DHEAD);
            float2 vf[8];
#pragma unroll
            for (int d = 0; d < 8; d++) vf[d] = __half22float2(vr[lane + 32 * d]);

#pragma unroll
            for (int i = 0; i < 4; i++) {
                if (j >= s0[i] && j < s1[i]) {
                    const float sc = s[i] * ATTN_SCALE;
                    const float mn = fmaxf(m[i], sc);
                    const float ce = __expf(m[i] - mn);
                    const float p = __expf(sc - mn);
                    l[i] = l[i] * ce + p;
#pragma unroll
                    for (int d = 0; d < 8; d++) {
                        accv[i][2 * d] = fmaf(accv[i][2 * d], ce, p * vf[d].x);
                        accv[i][2 * d + 1] = fmaf(accv[i][2 * d + 1], ce, p * vf[d].y);
                    }
                    m[i] = mn;
                }
            }
        }
        __syncthreads();
        if (ci + 2 < nch) load_chunk(bjmin + (ci + 2) * ACH, buf);
    }

#pragma unroll
    for (int i = 0; i < 4; i++) {
        const int q = q0 + i;
        const float inv = 1.0f / l[i];
        const float2* xr = (const float2*)(X + (size_t)q * DMODEL + hoff);
        __half2* hrow = (__half2*)(R1h + (size_t)q * DMODEL + hoff);
#pragma unroll
        for (int d = 0; d < 8; d++) {
            const float2 x2 = xr[lane + 32 * d];
            hrow[lane + 32 * d] = __floats2half2_rn(
                accv[i][2 * d] * inv + x2.x, accv[i][2 * d + 1] * inv + x2.y);
        }
    }
}

// ---------------------------------------------------------------------------
// kernel_launch
// ---------------------------------------------------------------------------
extern "C" void kernel_launch(void* const* d_in, const int* in_sizes, int n_in,
                              void* d_out, int out_size) {
    const float* X   = (const float*)d_in[0];
    const int*   nr  = (const int*)d_in[1];
    const float* Wq  = (const float*)d_in[2];
    const float* bq  = (const float*)d_in[3];
    const float* Wk  = (const float*)d_in[4];
    const float* bk  = (const float*)d_in[5];
    const float* Wv  = (const float*)d_in[6];
    const float* bv  = (const float*)d_in[7];
    const float* Wfc = (const float*)d_in[8];
    const float* bfc = (const float*)d_in[9];
    float* out = (float*)d_out;

    float *bqkv;
    __half *QKV, *Xh, *R1h, *W;
    cudaGetSymbolAddress((void**)&QKV, g_QKV);
    cudaGetSymbolAddress((void**)&bqkv, g_bqkv);
    cudaGetSymbolAddress((void**)&Xh, g_Xh);
    cudaGetSymbolAddress((void**)&R1h, g_R1h);
    cudaGetSymbolAddress((void**)&W, g_W);

    cudaFuncSetAttribute(gemm_f16<0>, cudaFuncAttributeMaxDynamicSharedMemorySize, GEMM_SMEM);
    cudaFuncSetAttribute(gemm_f16<1>, cudaFuncAttributeMaxDynamicSharedMemorySize, GEMM_SMEM);
    cudaFuncSetAttribute(attn_kernel, cudaFuncAttributeMaxDynamicSharedMemorySize, ATTN_SMEM);

    int nsm = 148;
    cudaDeviceGetAttribute(&nsm, cudaDevAttrMultiProcessorCount, 0);

    const int n4 = (NTOK * DMODEL) / 4;

    // prep
    seg_and_bias_kernel<<<16 + (QKV_N + 255) / 256, 256>>>(nr, in_sizes[1],
                                                           bq, bk, bv, bqkv);
    convert_h<<<n4 / 256, 256>>>(X, Xh, n4);
    dim3 tgrid4(DMODEL / 64, DMODEL / 64, 4);
    transpose_conv4<<<tgrid4, 256>>>(Wq, Wk, Wv, Wfc, W);

    // fused QKV projection -> fp16 (persistent)
    const int qkv_tiles = NTM * (QKV_N / GBN);
    gemm_f16<1><<<(qkv_tiles < nsm ? qkv_tiles : nsm), 256, GEMM_SMEM>>>(
        Xh, W, bqkv, nullptr, QKV, QKV_N, qkv_tiles);

    // attention -> R1h (fp16 context + X residual)
    dim3 agrid(NTOK / 32, NHEADS);
    attn_kernel<<<agrid, 256, ATTN_SMEM>>>(QKV, X, R1h);

    // FC: out = R1h + R1h @ Wfc + bfc (persistent)
    const int fc_tiles = NTM * (DMODEL / GBN);
    gemm_f16<0><<<(fc_tiles < nsm ? fc_tiles : nsm), 256, GEMM_SMEM>>>(
        R1h, W + (size_t)3 * DMODEL * DMODEL, bfc, R1h, out, DMODEL, fc_tiles);
}

// round 13
// speedup vs baseline: 1.4816x; 1.1077x over previous
#include <cuda_runtime.h>
#include <cuda_fp16.h>
#include <math.h>
#include <stdint.h>

// ---------------------------------------------------------------------------
// Self_Attention: N=4096 tokens, D=4096, H=8 heads, DH=512
// Round 13: GEMM re-tiled to 128x128 CTA (regs<=~130, 96KB smem) so 2 CTAs/SM
//           co-reside -> chunk-boundary stalls overlap (ncu: tensor 56%@occ12.5%).
//           Attention reverted to R10 (ACH=32). Prep unchanged.
// ---------------------------------------------------------------------------
#define NTOK 4096
#define DMODEL 4096
#define NHEADS 8
#define DHEAD 512
#define QKV_N (3 * DMODEL)
#define ATTN_SCALE 0.04419417382415922f  // 1/sqrt(512)

__device__ __half g_QKV[(size_t)NTOK * QKV_N];      // fp16 [token][Q|K|V]
__device__ float g_bqkv[QKV_N];
__device__ __half g_Xh[(size_t)NTOK * DMODEL];
__device__ __half g_R1h[(size_t)NTOK * DMODEL];
__device__ __half g_W[(size_t)4 * DMODEL * DMODEL]; // [Wq|Wk|Wv|Wfc], each [N,K] fp16
__device__ int g_seg_start[NTOK];
__device__ int g_seg_end[NTOK];

// ---------------------------------------------------------------------------
// PTX helpers
// ---------------------------------------------------------------------------
__device__ __forceinline__ uint32_t smem_u32(const void* p) {
    return (uint32_t)__cvta_generic_to_shared(p);
}
__device__ __forceinline__ uint32_t swz128(uint32_t off) {
    return off ^ ((off >> 3) & 0x70);
}
__device__ __forceinline__ void cp16(uint32_t s, const void* g) {
    asm volatile("cp.async.cg.shared.global [%0], [%1], 16;\n" :: "r"(s), "l"(g));
}
__device__ __forceinline__ void cp_commit() {
    asm volatile("cp.async.commit_group;\n" ::: "memory");
}
__device__ __forceinline__ void cp_wait0() {
    asm volatile("cp.async.wait_group 0;\n" ::: "memory");
}
__device__ __forceinline__ void cp_wait1() {
    asm volatile("cp.async.wait_group 1;\n" ::: "memory");
}
__device__ __forceinline__ void cp_wait2() {
    asm volatile("cp.async.wait_group 2;\n" ::: "memory");
}
__device__ __forceinline__ void ldsm4(uint32_t* r, uint32_t addr) {
    asm volatile("ldmatrix.sync.aligned.m8n8.x4.shared.b16 {%0,%1,%2,%3}, [%4];"
                 : "=r"(r[0]), "=r"(r[1]), "=r"(r[2]), "=r"(r[3]) : "r"(addr));
}
// fp32-accumulate MMA (the proven path)
__device__ __forceinline__ void mma_f16(float* d, const uint32_t* a,
                                        uint32_t b0, uint32_t b1) {
    asm volatile(
        "mma.sync.aligned.m16n8k16.row.col.f32.f16.f16.f32 "
        "{%0,%1,%2,%3}, {%4,%5,%6,%7}, {%8,%9}, {%0,%1,%2,%3};"
        : "+f"(d[0]), "+f"(d[1]), "+f"(d[2]), "+f"(d[3])
        : "r"(a[0]), "r"(a[1]), "r"(a[2]), "r"(a[3]), "r"(b0), "r"(b1));
}

// ---------------------------------------------------------------------------
// Merged prep: blocks 0..15 build segment table; blocks 16.. concat QKV bias.
// ---------------------------------------------------------------------------
__global__ void seg_and_bias_kernel(const int* __restrict__ nr, int count,
                                    const float* __restrict__ bq,
                                    const float* __restrict__ bk,
                                    const float* __restrict__ bv,
                                    float* __restrict__ bqkv) {
    const int b = blockIdx.x;
    if (b >= 16) {
        int i = (b - 16) * 256 + threadIdx.x;
        if (i < QKV_N)
            bqkv[i] = (i < DMODEL) ? bq[i]
                      : (i < 2 * DMODEL ? bk[i - DMODEL] : bv[i - 2 * DMODEL]);
        return;
    }
    __shared__ int starts[160];
    __shared__ int nseg;
    if (count > 128) count = 128;
    if (threadIdx.x == 0) {
        long long s32 = 0;
        for (int i = 0; i < count; i++) s32 += nr[i];
        int is64 = (s32 != (long long)NTOK) ? 1 : 0;
        int acc = 0;
        for (int i = 0; i < count; i++) {
            starts[i] = acc;
            acc += is64 ? nr[2 * i] : nr[i];
        }
        starts[count] = acc;
        nseg = count;
    }
    __syncthreads();
    const int ns = nseg;
    const int t = b * 256 + threadIdx.x;
    int lo = 0, hi = ns;
    while (hi - lo > 1) {
        int mid = (lo + hi) >> 1;
        if (starts[mid] <= t) lo = mid; else hi = mid;
    }
    g_seg_start[t] = starts[lo];
    g_seg_end[t] = starts[lo + 1];
}

// ---------------------------------------------------------------------------
// fp32 -> fp16 convert
// ---------------------------------------------------------------------------
__global__ __launch_bounds__(256)
void convert_h(const float* __restrict__ src, __half* __restrict__ dst, int n4) {
    int i = blockIdx.x * blockDim.x + threadIdx.x;
    if (i >= n4) return;
    float4 v = reinterpret_cast<const float4*>(src)[i];
    __half2 a = __floats2half2_rn(v.x, v.y);
    __half2 b = __floats2half2_rn(v.z, v.w);
    uint2 o;
    o.x = *reinterpret_cast<uint32_t*>(&a);
    o.y = *reinterpret_cast<uint32_t*>(&b);
    reinterpret_cast<uint2*>(dst)[i] = o;
}

// ---------------------------------------------------------------------------
// Vectorized weight transpose+convert: 64x64 tiles, grid.z=4 selects matrix.
// ---------------------------------------------------------------------------
__global__ __launch_bounds__(256)
void transpose_conv4(const float* __restrict__ W0, const float* __restrict__ W1,
                     const float* __restrict__ W2, const float* __restrict__ W3,
                     __half* __restrict__ T) {
    const float* W = (blockIdx.z == 0) ? W0 : (blockIdx.z == 1 ? W1
                     : (blockIdx.z == 2 ? W2 : W3));
    __half* dst = T + (size_t)blockIdx.z * DMODEL * DMODEL;
    __shared__ float sm[64][65];
    const int n0 = blockIdx.x * 64;
    const int k0 = blockIdx.y * 64;
    const int tid = threadIdx.x;
#pragma unroll
    for (int j = 0; j < 4; j++) {
        int u = tid + 256 * j;
        int kr = u >> 4;
        int c4 = (u & 15) * 4;
        float4 v = *reinterpret_cast<const float4*>(
            W + (size_t)(k0 + kr) * DMODEL + n0 + c4);
        sm[kr][c4 + 0] = v.x;
        sm[kr][c4 + 1] = v.y;
        sm[kr][c4 + 2] = v.z;
        sm[kr][c4 + 3] = v.w;
    }
    __syncthreads();
#pragma unroll
    for (int j = 0; j < 4; j++) {
        int u = tid + 256 * j;
        int nr = u >> 4;
        int kg = (u & 15) * 4;
        __half2 h0 = __floats2half2_rn(sm[kg + 0][nr], sm[kg + 1][nr]);
        __half2 h1 = __floats2half2_rn(sm[kg + 2][nr], sm[kg + 3][nr]);
        uint2 o;
        o.x = *reinterpret_cast<uint32_t*>(&h0);
        o.y = *reinterpret_cast<uint32_t*>(&h1);
        *reinterpret_cast<uint2*>(dst + (size_t)(n0 + nr) * DMODEL + k0 + kg) = o;
    }
}

// ---------------------------------------------------------------------------
// Persistent fp16 HMMA GEMM (fp32 acc), 2 CTAs/SM:
// CTA 128x128, 8 warps (4x2), warp 32x64, BK=64, 3-stage cp.async (96KB).
// ---------------------------------------------------------------------------
#define GBM 128
#define GBN 128
#define GBK 64
#define GK DMODEL
#define NCHUNK (GK / GBK)          // 64
#define A_BYTES 16384              // 128 rows x 128B
#define B_BYTES 16384
#define STAGE_BYTES (A_BYTES + B_BYTES)       // 32768
#define NSTAGE 3
#define GEMM_SMEM (NSTAGE * STAGE_BYTES)      // 98304 per CTA (2 CTAs/SM)
#define EPI_STRIDE 132
#define NTM (NTOK / GBM)           // 32

template <int HALF_OUT>
__global__ __launch_bounds__(256, 2)
void gemm_f16(const __half* __restrict__ Ah, const __half* __restrict__ Bh,
              const float* __restrict__ bias, const __half* __restrict__ resh,
              void* __restrict__ Cv, int Ntot, int ntiles) {
    extern __shared__ char smem[];
    const uint32_t sb = smem_u32(smem);
    const int tid = threadIdx.x;
    const int wid = tid >> 5;
    const int lane = tid & 31;
    const int warpM = wid >> 1;        // 0..3 -> 32-row slices
    const int warpN = wid & 1;         // 0..1 -> 64-col slices
    const int lrow = lane & 15;
    const int lcol = (lane >> 4) * 16;
    const size_t rowstride = (size_t)GK * 2;

    for (int tile = blockIdx.x; tile < ntiles; tile += gridDim.x) {
        const int tm = tile % NTM;
        const int tn = tile / NTM;
        const char* pAh = (const char*)(Ah + (size_t)tm * GBM * GK);
        const char* pBh = (const char*)(Bh + (size_t)tn * GBN * GK);

        auto issue_loads = [&](int chunk, int s) {
            const uint32_t base = sb + s * STAGE_BYTES;
            const size_t koff = (size_t)chunk * GBK * 2;   // 128 B
#pragma unroll
            for (int j = 0; j < 4; j++) {
                int u = tid + 256 * j;
                int row = u >> 3;
                int c = (u & 7) * 16;
                uint32_t so = swz128((uint32_t)(row * 128 + c));
                size_t go = (size_t)row * rowstride + koff + c;
                cp16(base + so, pAh + go);
                cp16(base + A_BYTES + so, pBh + go);
            }
            cp_commit();
        };

        float acc[2][8][4];
#pragma unroll
        for (int mt = 0; mt < 2; mt++)
#pragma unroll
            for (int nt = 0; nt < 8; nt++)
#pragma unroll
                for (int e = 0; e < 4; e++) acc[mt][nt][e] = 0.0f;

        issue_loads(0, 0);
        issue_loads(1, 1);
        issue_loads(2, 2);

        for (int i = 0; i < NCHUNK; i++) {
            if (i + 3 <= NCHUNK) cp_wait2();
            else if (i + 2 <= NCHUNK) cp_wait1();
            else cp_wait0();
            __syncthreads();
            const int s = i % NSTAGE;
            const uint32_t bA = sb + s * STAGE_BYTES;
            const uint32_t bB = bA + A_BYTES;

#pragma unroll
            for (int ks = 0; ks < 4; ks++) {
                const int kb = ks * 32 + lcol;
                uint32_t aH[2][4], bH[4][4];
#pragma unroll
                for (int mt = 0; mt < 2; mt++) {
                    int row = warpM * 32 + mt * 16 + lrow;
                    ldsm4(aH[mt], bA + swz128((uint32_t)(row * 128 + kb)));
                }
#pragma unroll
                for (int p = 0; p < 4; p++) {
                    int row = warpN * 64 + p * 16 + lrow;
                    ldsm4(bH[p], bB + swz128((uint32_t)(row * 128 + kb)));
                }
#pragma unroll
                for (int mt = 0; mt < 2; mt++) {
#pragma unroll
                    for (int nt = 0; nt < 8; nt++) {
                        const int p = nt >> 1;
                        const int o = nt & 1;
                        mma_f16(acc[mt][nt], aH[mt], bH[p][o], bH[p][o + 2]);
                    }
                }
            }
            __syncthreads();
            if (i + 3 < NCHUNK) issue_loads(i + 3, s);
        }
        __syncthreads();

        // ---- epilogue: regs -> smem -> coalesced out ----
        float* sf = reinterpret_cast<float*>(smem);
        const int g = lane >> 2;
        const int t2 = (lane & 3) * 2;
#pragma unroll
        for (int mt = 0; mt < 2; mt++) {
#pragma unroll
            for (int nt = 0; nt < 8; nt++) {
                int row = warpM * 32 + mt * 16 + g;
                int col = warpN * 64 + nt * 8 + t2;
                sf[row * EPI_STRIDE + col] = acc[mt][nt][0];
                sf[row * EPI_STRIDE + col + 1] = acc[mt][nt][1];
                sf[(row + 8) * EPI_STRIDE + col] = acc[mt][nt][2];
                sf[(row + 8) * EPI_STRIDE + col + 1] = acc[mt][nt][3];
            }
        }
        __syncthreads();

        // 256 threads: 2 threads per row, 64 cols each
        const int orow = tid >> 1;
        const int oc0 = (tid & 1) * 64;
        const size_t gbase = (size_t)(tm * GBM + orow) * Ntot + (size_t)tn * GBN + oc0;
        const size_t rbase = (size_t)(tm * GBM + orow) * DMODEL + (size_t)tn * GBN + oc0;
#pragma unroll
        for (int j = 0; j < 16; j++) {
            int col = oc0 + j * 4;
            float4 v;
            v.x = sf[orow * EPI_STRIDE + col + 0] + bias[tn * GBN + col + 0];
            v.y = sf[orow * EPI_STRIDE + col + 1] + bias[tn * GBN + col + 1];
            v.z = sf[orow * EPI_STRIDE + col + 2] + bias[tn * GBN + col + 2];
            v.w = sf[orow * EPI_STRIDE + col + 3] + bias[tn * GBN + col + 3];
            if (HALF_OUT) {
                __half2 h0 = __floats2half2_rn(v.x, v.y);
                __half2 h1 = __floats2half2_rn(v.z, v.w);
                uint2 o;
                o.x = *reinterpret_cast<uint32_t*>(&h0);
                o.y = *reinterpret_cast<uint32_t*>(&h1);
                *reinterpret_cast<uint2*>((__half*)Cv + gbase + j * 4) = o;
            } else {
                if (resh != nullptr) {
                    uint2 r2 = *reinterpret_cast<const uint2*>(resh + rbase + j * 4);
                    float2 ra = __half22float2(*reinterpret_cast<__half2*>(&r2.x));
                    float2 rb = __half22float2(*reinterpret_cast<__half2*>(&r2.y));
                    v.x += ra.x; v.y += ra.y; v.z += rb.x; v.w += rb.y;
                }
                *reinterpret_cast<float4*>((float*)Cv + gbase + j * 4) = v;
            }
        }
        __syncthreads();
    }
}

// ---------------------------------------------------------------------------
// Block-diagonal attention (R10 version): cp.async double-buffered smem K/V,
// Block = 32 queries x 1 head, ACH=32, 128KB smem.
// ---------------------------------------------------------------------------
#define ACH 32
#define KV_BYTES (ACH * DHEAD * 2)
#define ABUF_BYTES (2 * KV_BYTES)
#define ATTN_SMEM (2 * ABUF_BYTES)            // 128 KB

__global__ __launch_bounds__(256)
void attn_kernel(const __half* __restrict__ QKV, const float* __restrict__ X,
                 __half* __restrict__ R1h) {
    extern __shared__ char smem[];
    const uint32_t sb = smem_u32(smem);

    const int tid = threadIdx.x;
    const int lane = tid & 31;
    const int warp = tid >> 5;
    const int q0b = blockIdx.x * 32;
    const int q0 = q0b + warp * 4;
    const int h = blockIdx.y;
    const int hoff = h * DHEAD;

    const int bjmin = g_seg_start[q0b];
    const int bjmax = g_seg_end[q0b + 31];
    const int nch = (bjmax - bjmin + ACH - 1) / ACH;

    int s0[4], s1[4];
    __half2 q2[4][8];
#pragma unroll
    for (int i = 0; i < 4; i++) {
        const int q = q0 + i;
        s0[i] = g_seg_start[q];
        s1[i] = g_seg_end[q];
        const __half2* qrow = (const __half2*)(QKV + (size_t)q * QKV_N + hoff);
#pragma unroll
        for (int d = 0; d < 8; d++) q2[i][d] = qrow[lane + 32 * d];
    }
    const int wjmin = min(min(s0[0], s0[1]), min(s0[2], s0[3]));
    const int wjmax = max(max(s1[0], s1[1]), max(s1[2], s1[3]));

    float m[4] = {-1e30f, -1e30f, -1e30f, -1e30f};
    float l[4] = {0.f, 0.f, 0.f, 0.f};
    float accv[4][16];
#pragma unroll
    for (int i = 0; i < 4; i++)
#pragma unroll
        for (int d = 0; d < 16; d++) accv[i][d] = 0.0f;

    auto load_chunk = [&](int c, int buf) {
        const uint32_t kb = sb + buf * ABUF_BYTES;
        const uint32_t vb = kb + KV_BYTES;
#pragma unroll
        for (int j = 0; j < 8; j++) {
            int e = tid + 256 * j;
            int r = e >> 6;
            int u = (e & 63) * 16;
            int rc = min(c + r, bjmax - 1);
            const char* kg = (const char*)(QKV + (size_t)rc * QKV_N + DMODEL + hoff) + u;
            const char* vg = (const char*)(QKV + (size_t)rc * QKV_N + 2 * DMODEL + hoff) + u;
            cp16(kb + r * 1024 + u, kg);
            cp16(vb + r * 1024 + u, vg);
        }
        cp_commit();
    };

    load_chunk(bjmin, 0);
    if (nch > 1) load_chunk(bjmin + ACH, 1);

    for (int ci = 0; ci < nch; ci++) {
        const int c = bjmin + ci * ACH;
        const int nrows = min(ACH, bjmax - c);
        if (ci + 1 < nch) cp_wait1(); else cp_wait0();
        __syncthreads();

        const int buf = ci & 1;
        const __half* Ks = (const __half*)(smem + buf * ABUF_BYTES);
        const __half* Vs = (const __half*)(smem + buf * ABUF_BYTES + KV_BYTES);

        const int j0 = max(c, wjmin);
        const int j1 = min(c + nrows, wjmax);
        for (int j = j0; j < j1; j++) {
            const __half2* kr = (const __half2*)(Ks + (j - c) * DHEAD);
            float s[4] = {0.f, 0.f, 0.f, 0.f};
#pragma unroll
            for (int d = 0; d < 8; d++) {
                const float2 kf = __half22float2(kr[lane + 32 * d]);
#pragma unroll
                for (int i = 0; i < 4; i++) {
                    const float2 qf = __half22float2(q2[i][d]);
                    s[i] = fmaf(qf.x, kf.x, s[i]);
                    s[i] = fmaf(qf.y, kf.y, s[i]);
                }
            }
#pragma unroll
            for (int off = 16; off > 0; off >>= 1) {
#pragma unroll
                for (int i = 0; i < 4; i++)
                    s[i] += __shfl_xor_sync(0xFFFFFFFFu, s[i], off);
            }

            const __half2* vr = (const __half2*)(Vs + (j - c) * DHEAD);
            float2 vf[8];
#pragma unroll
            for (int d = 0; d < 8; d++) vf[d] = __half22float2(vr[lane + 32 * d]);

#pragma unroll
            for (int i = 0; i < 4; i++) {
                if (j >= s0[i] && j < s1[i]) {
                    const float sc = s[i] * ATTN_SCALE;
                    const float mn = fmaxf(m[i], sc);
                    const float ce = __expf(m[i] - mn);
                    const float p = __expf(sc - mn);
                    l[i] = l[i] * ce + p;
#pragma unroll
                    for (int d = 0; d < 8; d++) {
                        accv[i][2 * d] = fmaf(accv[i][2 * d], ce, p * vf[d].x);
                        accv[i][2 * d + 1] = fmaf(accv[i][2 * d + 1], ce, p * vf[d].y);
                    }
                    m[i] = mn;
                }
            }
        }
        __syncthreads();
        if (ci + 2 < nch) load_chunk(bjmin + (ci + 2) * ACH, buf);
    }

#pragma unroll
    for (int i = 0; i < 4; i++) {
        const int q = q0 + i;
        const float inv = 1.0f / l[i];
        const float2* xr = (const float2*)(X + (size_t)q * DMODEL + hoff);
        __half2* hrow = (__half2*)(R1h + (size_t)q * DMODEL + hoff);
#pragma unroll
        for (int d = 0; d < 8; d++) {
            const float2 x2 = xr[lane + 32 * d];
            hrow[lane + 32 * d] = __floats2half2_rn(
                accv[i][2 * d] * inv + x2.x, accv[i][2 * d + 1] * inv + x2.y);
        }
    }
}

// ---------------------------------------------------------------------------
// kernel_launch
// ---------------------------------------------------------------------------
extern "C" void kernel_launch(void* const* d_in, const int* in_sizes, int n_in,
                              void* d_out, int out_size) {
    const float* X   = (const float*)d_in[0];
    const int*   nr  = (const int*)d_in[1];
    const float* Wq  = (const float*)d_in[2];
    const float* bq  = (const float*)d_in[3];
    const float* Wk  = (const float*)d_in[4];
    const float* bk  = (const float*)d_in[5];
    const float* Wv  = (const float*)d_in[6];
    const float* bv  = (const float*)d_in[7];
    const float* Wfc = (const float*)d_in[8];
    const float* bfc = (const float*)d_in[9];
    float* out = (float*)d_out;

    float *bqkv;
    __half *QKV, *Xh, *R1h, *W;
    cudaGetSymbolAddress((void**)&QKV, g_QKV);
    cudaGetSymbolAddress((void**)&bqkv, g_bqkv);
    cudaGetSymbolAddress((void**)&Xh, g_Xh);
    cudaGetSymbolAddress((void**)&R1h, g_R1h);
    cudaGetSymbolAddress((void**)&W, g_W);

    cudaFuncSetAttribute(gemm_f16<0>, cudaFuncAttributeMaxDynamicSharedMemorySize, GEMM_SMEM);
    cudaFuncSetAttribute(gemm_f16<1>, cudaFuncAttributeMaxDynamicSharedMemorySize, GEMM_SMEM);
    cudaFuncSetAttribute(attn_kernel, cudaFuncAttributeMaxDynamicSharedMemorySize, ATTN_SMEM);

    int nsm = 148;
    cudaDeviceGetAttribute(&nsm, cudaDevAttrMultiProcessorCount, 0);

    const int n4 = (NTOK * DMODEL) / 4;

    // prep
    seg_and_bias_kernel<<<16 + (QKV_N + 255) / 256, 256>>>(nr, in_sizes[1],
                                                           bq, bk, bv, bqkv);
    convert_h<<<n4 / 256, 256>>>(X, Xh, n4);
    dim3 tgrid4(DMODEL / 64, DMODEL / 64, 4);
    transpose_conv4<<<tgrid4, 256>>>(Wq, Wk, Wv, Wfc, W);

    // fused QKV projection -> fp16 (persistent, 2 CTAs/SM)
    const int qkv_tiles = NTM * (QKV_N / GBN);
    const int qkv_grid = (qkv_tiles < 2 * nsm) ? qkv_tiles : 2 * nsm;
    gemm_f16<1><<<qkv_grid, 256, GEMM_SMEM>>>(Xh, W, bqkv, nullptr, QKV, QKV_N, qkv_tiles);

    // attention -> R1h (fp16 context + X residual)
    dim3 agrid(NTOK / 32, NHEADS);
    attn_kernel<<<agrid, 256, ATTN_SMEM>>>(QKV, X, R1h);

    // FC: out = R1h + R1h @ Wfc + bfc (persistent, 2 CTAs/SM)
    const int fc_tiles = NTM * (DMODEL / GBN);
    const int fc_grid = (fc_tiles < 2 * nsm) ? fc_tiles : 2 * nsm;
    gemm_f16<0><<<fc_grid, 256, GEMM_SMEM>>>(
        R1h, W + (size_t)3 * DMODEL * DMODEL, bfc, R1h, out, DMODEL, fc_tiles);
}